// round 2
// baseline (speedup 1.0000x reference)
#include <cuda_runtime.h>
#include <cuda_fp16.h>
#include <cstdint>

// ============================================================================
// Problem constants (dataset: n1=n2=8192, d=256)
// ============================================================================
#define D_DIM 256
#define N_MAX 8192
#define SQRT3F 1.7320508075688772f

// Scratch (allocation-free rule: __device__ globals)
__device__ __align__(128) __half g_ah[N_MAX * D_DIM];
__device__ __align__(128) __half g_al[N_MAX * D_DIM];
__device__ __align__(128) __half g_bh[N_MAX * D_DIM];
__device__ __align__(128) __half g_bl[N_MAX * D_DIM];
__device__ __align__(128) float  g_sq1[N_MAX];
__device__ __align__(128) float  g_sq2[N_MAX];
__device__ __align__(128) float  g_part[32 * D_DIM];
__device__ __align__(128) float  g_adj[D_DIM];

// ============================================================================
// Portable PTX helpers (sm_80-era ISA only: cp.async / ldmatrix / mma.sync)
// ============================================================================
__device__ __forceinline__ uint32_t smem_u32(const void* p) {
    uint32_t a;
    asm("{ .reg .u64 t; cvta.to.shared.u64 t, %1; cvt.u32.u64 %0, t; }"
        : "=r"(a) : "l"(p));
    return a;
}

__device__ __forceinline__ void cp16(uint32_t dst, const void* src) {
    asm volatile("cp.async.cg.shared.global [%0], [%1], 16;"
                 :: "r"(dst), "l"(src) : "memory");
}
#define CP_COMMIT() asm volatile("cp.async.commit_group;" ::: "memory")
#define CP_WAIT1()  asm volatile("cp.async.wait_group 1;" ::: "memory")

#define LDSM_X4(r, addr) \
    asm volatile("ldmatrix.sync.aligned.m8n8.x4.shared.b16 {%0,%1,%2,%3}, [%4];" \
                 : "=r"((r)[0]), "=r"((r)[1]), "=r"((r)[2]), "=r"((r)[3]) \
                 : "r"(addr))

__device__ __forceinline__ void mma16816(float* c, const uint32_t* a,
                                         const uint32_t* b) {
    asm volatile(
        "mma.sync.aligned.m16n8k16.row.col.f32.f16.f16.f32 "
        "{%0,%1,%2,%3}, {%4,%5,%6,%7}, {%8,%9}, {%0,%1,%2,%3};"
        : "+f"(c[0]), "+f"(c[1]), "+f"(c[2]), "+f"(c[3])
        : "r"(a[0]), "r"(a[1]), "r"(a[2]), "r"(a[3]),
          "r"(b[0]), "r"(b[1]));
}

// ============================================================================
// Prep kernels
// ============================================================================
__global__ void k_mean_partial(const float* __restrict__ x1, int n1) {
    int d = threadIdx.x, b = blockIdx.x;
    float s = 0.f;
    for (int r = b; r < n1; r += 32) s += x1[(size_t)r * D_DIM + d];
    g_part[b * D_DIM + d] = s;
}

__global__ void k_mean_final(int n1) {
    int d = threadIdx.x;
    float s = 0.f;
#pragma unroll
    for (int b = 0; b < 32; b++) s += g_part[b * D_DIM + d];
    g_adj[d] = s / (float)n1;
}

// Center, scale, split fp32 -> fp16 hi + fp16 lo, row sqnorm of recomposed value.
__global__ void k_normalize(const float* __restrict__ x, const float* __restrict__ ls,
                            int which) {
    __shared__ float red[D_DIM];
    __half* hi = which ? g_bh : g_ah;
    __half* lo = which ? g_bl : g_al;
    float*  sq = which ? g_sq2 : g_sq1;
    int r = blockIdx.x, d = threadIdx.x;
    size_t idx = (size_t)r * D_DIM + d;
    float v = (x[idx] - g_adj[d]) / ls[d];
    __half h = __float2half_rn(v);
    __half l = __float2half_rn(v - __half2float(h));
    hi[idx] = h;
    lo[idx] = l;
    float vh = __half2float(h) + __half2float(l);
    red[d] = vh * vh;
    __syncthreads();
#pragma unroll
    for (int s = D_DIM / 2; s > 0; s >>= 1) {
        if (d < s) red[d] += red[d + s];
        __syncthreads();
    }
    if (d == 0) sq[r] = red[0];
}

// ============================================================================
// Fused GEMM + Matern epilogue (mma.sync m16n8k16, fp16 hi/lo split)
//
// CTA tile 128x128, 8 warps in 2x4 grid, warp tile 64x32.
// K = 256 in 8 chunks of 32, cp.async double-buffered.
// Smem rows padded to 80B -> conflict-free ldmatrix (gcd(5,8)=1 permutation).
// 3 accumulating HMMA passes per k-step: Ah*Bh + Ah*Bl + Al*Bh.
// ============================================================================
#define ROW_B    80                    // padded row stride (32 halves used, 40 alloc)
#define TILE_B   (128 * ROW_B)         // 10240 B per tile
#define STAGE_B  (4 * TILE_B)          // Ah | Al | Bh | Bl
#define SMEM_REQ (2 * STAGE_B + 1536)  // + sq1/sq2 + align slack

__global__ void __launch_bounds__(256, 2)
k_matern_gemm(float* __restrict__ out, int n2) {
    extern __shared__ char smem_raw[];
    uint32_t sbase_u = smem_u32(smem_raw);
    uint32_t abase = (sbase_u + 127u) & ~127u;
    char* ap = smem_raw + (abase - sbase_u);

    const int tid  = threadIdx.x;
    const int lane = tid & 31;
    const int wid  = tid >> 5;
    const int wm   = wid >> 2;   // 0..1 : 64-row slice
    const int wn   = wid & 3;    // 0..3 : 32-col slice
    const int bX   = blockIdx.x;
    const int bY   = blockIdx.y;

    float* s_sq1 = reinterpret_cast<float*>(ap + 2 * STAGE_B);
    float* s_sq2 = reinterpret_cast<float*>(ap + 2 * STAGE_B + 512);
    if (tid < 128) {
        s_sq1[tid] = g_sq1[(size_t)bY * 128 + tid];
        s_sq2[tid] = g_sq2[(size_t)bX * 128 + tid];
    }

    const __half* __restrict__ pAh = g_ah + (size_t)bY * 128 * D_DIM;
    const __half* __restrict__ pAl = g_al + (size_t)bY * 128 * D_DIM;
    const __half* __restrict__ pBh = g_bh + (size_t)bX * 128 * D_DIM;
    const __half* __restrict__ pBl = g_bl + (size_t)bX * 128 * D_DIM;

    // ---- async stage loader: 4 tiles x 512 x 16B chunks, 8 cp.async/thread ----
    auto load_stage = [&](int buf, int kc) {
        uint32_t sbuf = abase + (uint32_t)buf * STAGE_B;
        const __half* srcs[4] = { pAh, pAl, pBh, pBl };
#pragma unroll
        for (int t4 = 0; t4 < 4; t4++) {
            const __half* src = srcs[t4];
#pragma unroll
            for (int i = 0; i < 2; i++) {
                int idx = tid + i * 256;            // 0..511
                int row = idx >> 2;                 // 0..127
                int g   = idx & 3;                  // 16B group in 64B chunk row
                uint32_t daddr = sbuf + (uint32_t)t4 * TILE_B
                               + (uint32_t)(row * ROW_B + g * 16);
                cp16(daddr, src + (size_t)row * D_DIM + kc * 32 + g * 8);
            }
        }
    };

    float acc[4][4][4];
#pragma unroll
    for (int i = 0; i < 4; i++)
#pragma unroll
        for (int j = 0; j < 4; j++)
#pragma unroll
            for (int e = 0; e < 4; e++) acc[i][j][e] = 0.f;

    load_stage(0, 0);
    CP_COMMIT();

    const int NCHUNK = D_DIM / 32;   // 8
    for (int c = 0; c < NCHUNK; c++) {
        if (c + 1 < NCHUNK) load_stage((c + 1) & 1, c + 1);
        CP_COMMIT();
        CP_WAIT1();
        __syncthreads();

        uint32_t sA  = abase + (uint32_t)(c & 1) * STAGE_B;
        uint32_t sB  = sA + 2 * TILE_B;

#pragma unroll
        for (int s = 0; s < 2; s++) {            // two k16 steps per 32-chunk
            // ---- A fragments (hi+lo, 4 m16 tiles) ----
            uint32_t ah[4][4], al[4][4];
            int arow = wm * 64 + (lane & 15);
            int ag   = s * 2 + (lane >> 4);
#pragma unroll
            for (int mt = 0; mt < 4; mt++) {
                uint32_t aaddr = sA + (uint32_t)((arow + mt * 16) * ROW_B + ag * 16);
                LDSM_X4(ah[mt], aaddr);
                LDSM_X4(al[mt], aaddr + TILE_B);
            }
            // ---- B fragments (hi+lo, 2 n16 groups), then 48 HMMA ----
            int t  = lane >> 3;
            int bn = wn * 32 + ((t >> 1) << 3) + (lane & 7);
            int bg = s * 2 + (t & 1);
#pragma unroll
            for (int nt2 = 0; nt2 < 2; nt2++) {
                uint32_t baddr = sB + (uint32_t)((bn + nt2 * 16) * ROW_B + bg * 16);
                uint32_t bh[4], bl[4];
                LDSM_X4(bh, baddr);
                LDSM_X4(bl, baddr + TILE_B);
#pragma unroll
                for (int mt = 0; mt < 4; mt++) {
                    mma16816(acc[mt][nt2 * 2],     ah[mt], bh);
                    mma16816(acc[mt][nt2 * 2],     ah[mt], bl);
                    mma16816(acc[mt][nt2 * 2],     al[mt], bh);
                    mma16816(acc[mt][nt2 * 2 + 1], ah[mt], bh + 2);
                    mma16816(acc[mt][nt2 * 2 + 1], ah[mt], bl + 2);
                    mma16816(acc[mt][nt2 * 2 + 1], al[mt], bh + 2);
                }
            }
        }
        __syncthreads();   // protect stage (c&1) before it is overwritten at c+1
    }

    // ---- fused Matern epilogue ----
    const int r0 = lane >> 2;
    const int c0 = 2 * (lane & 3);
#pragma unroll
    for (int mt = 0; mt < 4; mt++) {
        int row_l = wm * 64 + mt * 16 + r0;
        int row_g = bY * 128 + row_l;
        float sqa0 = s_sq1[row_l];
        float sqa8 = s_sq1[row_l + 8];
        float* orow0 = out + (size_t)row_g * (size_t)n2 + (size_t)bX * 128;
        float* orow8 = orow0 + 8u * (size_t)n2;
#pragma unroll
        for (int nt = 0; nt < 4; nt++) {
            int col_l = wn * 32 + nt * 8 + c0;
            float sqb0 = s_sq2[col_l];
            float sqb1 = s_sq2[col_l + 1];
            const float* a = acc[mt][nt];
            float4 res;
            {
                float d2 = fmaf(-2.f, a[0], sqa0 + sqb0);
                d2 = fmaxf(d2, 1e-30f);
                float t = SQRT3F * (d2 * rsqrtf(d2));
                res.x = (1.f + t) * __expf(-t);
            }
            {
                float d2 = fmaf(-2.f, a[1], sqa0 + sqb1);
                d2 = fmaxf(d2, 1e-30f);
                float t = SQRT3F * (d2 * rsqrtf(d2));
                res.y = (1.f + t) * __expf(-t);
            }
            {
                float d2 = fmaf(-2.f, a[2], sqa8 + sqb0);
                d2 = fmaxf(d2, 1e-30f);
                float t = SQRT3F * (d2 * rsqrtf(d2));
                res.z = (1.f + t) * __expf(-t);
            }
            {
                float d2 = fmaf(-2.f, a[3], sqa8 + sqb1);
                d2 = fmaxf(d2, 1e-30f);
                float t = SQRT3F * (d2 * rsqrtf(d2));
                res.w = (1.f + t) * __expf(-t);
            }
            *reinterpret_cast<float2*>(orow0 + col_l) = make_float2(res.x, res.y);
            *reinterpret_cast<float2*>(orow8 + col_l) = make_float2(res.z, res.w);
        }
    }
}

// ============================================================================
// kernel_launch
// ============================================================================
extern "C" void kernel_launch(void* const* d_in, const int* in_sizes, int n_in,
                              void* d_out, int out_size) {
    const float* x1 = (const float*)d_in[0];
    const float* x2 = (const float*)d_in[1];
    const float* ls = (const float*)d_in[2];
    float* out = (float*)d_out;

    int d  = in_sizes[2];            // 256
    int n1 = in_sizes[0] / d;        // 8192
    int n2 = in_sizes[1] / d;        // 8192

    k_mean_partial<<<32, D_DIM>>>(x1, n1);
    k_mean_final<<<1, D_DIM>>>(n1);
    k_normalize<<<n1, D_DIM>>>(x1, ls, 0);
    k_normalize<<<n2, D_DIM>>>(x2, ls, 1);

    static bool attr_set = false;
    if (!attr_set) {
        cudaFuncSetAttribute(k_matern_gemm,
                             cudaFuncAttributeMaxDynamicSharedMemorySize, SMEM_REQ);
        attr_set = true;
    }
    dim3 grid(n2 / 128, n1 / 128);
    k_matern_gemm<<<grid, 256, SMEM_REQ>>>(out, n2);
}